// round 17
// baseline (speedup 1.0000x reference)
#include <cuda_runtime.h>
#include <cuda_bf16.h>
#include <math.h>
#include <stdint.h>

#define HH 64
#define WWD 192
#define HWX (HH*WWD)       // 12288
#define HP 66
#define WP 194
#define PP (HP*WP)         // 12804
#define CIN 256
#define CO 128
#define MT 64
#define NGB (HWX/MT)       // 192 gemm blocks
#define RS 40              // smem row pitch in bf16 (80B): conflict-free ldmatrix

// prep fat-kernel partition
#define NB_TRANS 3208      // 401 x 8 transpose blocks
#define NB_WTS   48        // weights blocks
#define NB_WSPL  265       // wsplit blocks
#define NB_PREP  (NB_TRANS + NB_WTS + NB_WSPL)

// ---------------- scratch (device globals; no allocation) ----------------
__device__ float g_xT[PP*CIN];          // padded x, pixel-major (P, Cin)
__device__ int   g_gn[HWX];             // tap-entry count per pixel (6..9)
__device__ int4  g_tap[HWX*9];          // slots 0-5: side taps (fixed); 6+: border centers
__device__ float g_rcT[9*CIN];          // range_out transposed tap-major
__device__ __nv_bfloat16 g_y1[HWX*CIN];   // gather out hi
__device__ __nv_bfloat16 g_y2[HWX*CIN];   // gather out lo
__device__ __nv_bfloat16 g_w1h[CO*CIN], g_w1l[CO*CIN];
__device__ __nv_bfloat16 g_w2h[CO*CO],  g_w2l[CO*CO];
__device__ __nv_bfloat16 g_w3h[CO*CO],  g_w3l[CO*CO];
__device__ __nv_bfloat16 g_z1h[HWX*CO], g_z1l[HWX*CO];
__device__ __nv_bfloat16 g_z2h[HWX*CO], g_z2l[HWX*CO];
__device__ float g_C1[HWX*CO];
__device__ float g_C2[HWX*CO];
__device__ float g_C3[HWX*CO];
__device__ float g_psum[NGB*CO];
__device__ float g_psq[NGB*CO];
__device__ float g_bn[3*2*CO];

// ---------------- helpers ----------------
__device__ __forceinline__ uint32_t s2u(const void* p) {
    uint32_t r;
    asm("{ .reg .u64 t; cvta.to.shared.u64 t, %1; cvt.u32.u64 %0, t; }" : "=r"(r) : "l"(p));
    return r;
}
__device__ __forceinline__ void ldmx4(uint32_t* r, uint32_t addr) {
    asm volatile("ldmatrix.sync.aligned.m8n8.x4.shared.b16 {%0,%1,%2,%3}, [%4];"
                 : "=r"(r[0]), "=r"(r[1]), "=r"(r[2]), "=r"(r[3]) : "r"(addr));
}
__device__ __forceinline__ void mma16816(float* d, const uint32_t* a, uint32_t b0, uint32_t b1) {
    asm volatile(
        "mma.sync.aligned.m16n8k16.row.col.f32.bf16.bf16.f32 "
        "{%0,%1,%2,%3}, {%4,%5,%6,%7}, {%8,%9}, {%0,%1,%2,%3};"
        : "+f"(d[0]), "+f"(d[1]), "+f"(d[2]), "+f"(d[3])
        : "r"(a[0]), "r"(a[1]), "r"(a[2]), "r"(a[3]), "r"(b0), "r"(b1));
}
__device__ __forceinline__ void split_bf16(float v, __nv_bfloat16& h, __nv_bfloat16& l) {
    h = __float2bfloat16(v);
    l = __float2bfloat16(v - __bfloat162float(h));
}

// ---------------- 1) fused prep: pad-transpose | tap windows | weight splits -----
__global__ void k_prep(const float* __restrict__ x, const float* __restrict__ x_range,
                       const float* __restrict__ w1, const float* __restrict__ w2,
                       const float* __restrict__ w3, const float* __restrict__ rc) {
    __shared__ float s[32][33];
    int b = blockIdx.x;
    int tid = threadIdx.x;
    if (b < NB_TRANS) {
        // ---- pad + transpose x: (Cin,H,W) -> (P, Cin) ----
        int ptile = (b % 401) * 32;
        int ctile = (b / 401) * 32;
        int tx = tid & 31, ty = tid >> 5;   // 32 x 8
        #pragma unroll
        for (int i = 0; i < 32; i += 8) {
            int c = ctile + ty + i;
            int p = ptile + tx;
            float v = 0.f;
            if (p < PP) {
                int ph = p / WP, pw = p % WP;
                if (ph >= 1 && ph <= HH && pw >= 1 && pw <= WWD)
                    v = x[c*HWX + (ph-1)*WWD + (pw-1)];
            }
            s[ty+i][tx] = v;
        }
        __syncthreads();
        #pragma unroll
        for (int i = 0; i < 32; i += 8) {
            int p = ptile + ty + i;
            if (p < PP) g_xT[p*CIN + ctile + tx] = s[tx][ty+i];
        }
    } else if (b < NB_TRANS + NB_WTS) {
        // ---- per-pixel dense tap windows ----
        int p = (b - NB_TRANS) * 256 + tid;
        int h = p / WWD, w = p % WWD;
        float off = 3.0f / (1.0f + expf(-x_range[p]));
        float v0 = (float)((h+1)*WP + (w+1));
        const float PM1 = (float)(PP - 1);
        int cc = 6;
        #pragma unroll
        for (int t = 0; t < 9; t++) {
            float xo = (float)(t % 3 - 1);
            float yo = (float)(t / 3 - 1);
            float pre   = v0 + xo + yo*(float)WP;
            float ofv   = off*xo + yo*(float)WP;
            float after = pre + ofv;
            float avf  = fminf(fmaxf(pre + floorf(ofv), 0.f), PM1);
            float avf1 = fminf(fmaxf(avf + xo, 0.f), PM1);
            float avc  = fminf(fmaxf(pre + ceilf(ofv), 0.f), PM1);
            float avc1 = fminf(fmaxf(avc + xo, 0.f), PM1);
            float s1 = fabsf((after - avf)  / (float)WP);
            float s2 = fabsf((avc1 - after) / (float)WP);
            int   id4[4];
            float w4[4];
            id4[0] = (int)avf;  w4[0] = s1 * fabsf(after - avf);
            id4[1] = (int)avf1; w4[1] = s1 * fabsf(avf1 - after);
            id4[2] = (int)avc1; w4[2] = s2 * fabsf(after - avc1);
            id4[3] = (int)avc;  w4[3] = s2 * fabsf(avc - after);
            bool center = ((t % 3) == 1);
            bool any = (w4[0] != 0.f) | (w4[1] != 0.f) | (w4[2] != 0.f) | (w4[3] != 0.f);
            if (center && !any) continue;   // interior center taps: exactly zero
            int base = min(min(id4[0], id4[1]), min(id4[2], id4[3]));
            base = min(base, PP - 3);
            float w0 = 0.f, w1s = 0.f, w2s = 0.f;
            #pragma unroll
            for (int j = 0; j < 4; j++) {
                int d = id4[j] - base;
                w0  += (d == 0) ? w4[j] : 0.f;
                w1s += (d == 1) ? w4[j] : 0.f;
                w2s += (d == 2) ? w4[j] : 0.f;
            }
            int slot;
            if (!center) {
                slot = (t > 1 ? t - 1 : t);
                slot = (slot > 2 ? slot - 1 : slot);
                slot = (slot > 4 ? slot - 1 : slot);
            } else {
                slot = cc++;
            }
            g_tap[p*9 + slot] = make_int4(base | (t << 16),
                                          __float_as_int(w0), __float_as_int(w1s), __float_as_int(w2s));
        }
        g_gn[p] = cc;
    } else {
        // ---- weight splits + rc transpose ----
        int i = (b - NB_TRANS - NB_WTS) * 256 + tid;   // 0..67839
        if (i < CO*CIN) {
            split_bf16(w1[i], g_w1h[i], g_w1l[i]);
        } else if (i < CO*CIN + CO*CO) {
            int j = i - CO*CIN;
            split_bf16(w2[j], g_w2h[j], g_w2l[j]);
        } else if (i < CO*CIN + 2*CO*CO) {
            int j = i - CO*CIN - CO*CO;
            split_bf16(w3[j], g_w3h[j], g_w3l[j]);
        } else {
            int j = i - (CO*CIN + 2*CO*CO);       // 0..2303
            int t = j >> 8, c = j & 255;
            g_rcT[t*CIN + c] = rc[c*9 + t];
        }
    }
}

// ---------------- 3) gather: warp per (pixel, channel-half), zero smem ----------
__global__ __launch_bounds__(256, 5) void k_gather() {
    int tid = threadIdx.x, lane = tid & 31, wid = tid >> 5;
    int gw = blockIdx.x * 8 + wid;            // 0..24575
    int p = gw >> 1;
    int cb = (gw & 1) * 128 + lane * 4;
    int cnt = g_gn[p];                        // warp-uniform
    float4 acc = make_float4(0.f, 0.f, 0.f, 0.f);
    #pragma unroll
    for (int s = 0; s < 6; s++) {
        const int slot_tap = (s < 2 ? (s == 0 ? 0 : 2) :
                              s < 4 ? (s == 2 ? 3 : 5) :
                                      (s == 4 ? 6 : 8));   // compile-time per iter
        int4 en = g_tap[p*9 + s];             // warp-uniform LDG.128
        int base = en.x & 0xFFFF;
        float w0 = __int_as_float(en.y), w1 = __int_as_float(en.z), w2 = __int_as_float(en.w);
        const float* rp = &g_xT[base*CIN + cb];
        float4 v0 = *(const float4*)rp;
        float4 v1 = *(const float4*)(rp + CIN);
        float4 v2 = *(const float4*)(rp + 2*CIN);
        float4 r = *(const float4*)&g_rcT[slot_tap*CIN + cb];   // static addr, L1-hot
        acc.x += r.x * (w0*v0.x + w1*v1.x + w2*v2.x);
        acc.y += r.y * (w0*v0.y + w1*v1.y + w2*v2.y);
        acc.z += r.z * (w0*v0.z + w1*v1.z + w2*v2.z);
        acc.w += r.w * (w0*v0.w + w1*v1.w + w2*v2.w);
    }
    for (int e = 6; e < cnt; e++) {           // border-row center taps only (rare)
        int4 en = g_tap[p*9 + e];
        int base = en.x & 0xFFFF;
        int tap  = en.x >> 16;
        float w0 = __int_as_float(en.y), w1 = __int_as_float(en.z), w2 = __int_as_float(en.w);
        const float* rp = &g_xT[base*CIN + cb];
        float4 v0 = *(const float4*)rp;
        float4 v1 = *(const float4*)(rp + CIN);
        float4 v2 = *(const float4*)(rp + 2*CIN);
        float4 r = *(const float4*)&g_rcT[tap*CIN + cb];
        acc.x += r.x * (w0*v0.x + w1*v1.x + w2*v2.x);
        acc.y += r.y * (w0*v0.y + w1*v1.y + w2*v2.y);
        acc.z += r.z * (w0*v0.z + w1*v1.z + w2*v2.z);
        acc.w += r.w * (w0*v0.w + w1*v1.w + w2*v2.w);
    }
    union { __nv_bfloat162 b2[2]; uint2 u; } hv, lv;
    split_bf16(acc.x, hv.b2[0].x, lv.b2[0].x);
    split_bf16(acc.y, hv.b2[0].y, lv.b2[0].y);
    split_bf16(acc.z, hv.b2[1].x, lv.b2[1].x);
    split_bf16(acc.w, hv.b2[1].y, lv.b2[1].y);
    *(uint2*)&g_y1[p*CIN + cb] = hv.u;
    *(uint2*)&g_y2[p*CIN + cb] = lv.u;
}

// ---------------- 4) mma.sync bf16 GEMM + fused BN column partials ----------
// Block 64x128, 8 warps (wm 0..1 x wn 0..3), warp tile 32x32, K-chunk 32,
// double-buffered smem, 80B row pitch. Epilogue reduces its own 64 rows.
__global__ __launch_bounds__(256, 2) void k_gemm_tc(
    const __nv_bfloat16* __restrict__ Ah, const __nv_bfloat16* __restrict__ Al,
    const __nv_bfloat16* __restrict__ Bh, const __nv_bfloat16* __restrict__ Bl,
    float* __restrict__ C, int K)
{
    __shared__ __align__(16) union SmU {
        struct { __nv_bfloat16 A[2][MT*RS]; __nv_bfloat16 B[2][128*RS]; } m;
        struct { float sred[16][CO]; float sqred[16][CO]; } r;
    } sm;
    int t = threadIdx.x;            // 256
    int lane = t & 31, wid = t >> 5;
    int wm = wid >> 2, wn = wid & 3;
    int m0 = blockIdx.x * MT;

    int cpp = K >> 5;
    int nch = 3 * cpp;

    int lr = t >> 2, lc = (t & 3) * 8;   // A/B global-load row, k-offset

    float acc[2][4][4];
    #pragma unroll
    for (int mi = 0; mi < 2; mi++)
        #pragma unroll
        for (int nj = 0; nj < 4; nj++)
            #pragma unroll
            for (int q = 0; q < 4; q++) acc[mi][nj][q] = 0.f;

    int a_row = wm*32 + (lane & 7) + (((lane >> 3) & 1) << 3);
    int a_col = ((lane >> 4) & 1) << 3;
    int b_row = wn*32 + (lane & 7) + (((lane >> 4) & 1) << 3);
    int b_col = ((lane >> 3) & 1) << 3;

    uint32_t sAu0 = s2u(&sm.m.A[0][0]), sBu0 = s2u(&sm.m.B[0][0]);
    const uint32_t bufA = MT*RS*2, bufB = 128*RS*2;

    uint4 ra, rb0, rb1;
    {
        const uint4* As = (const uint4*)Ah;
        const uint4* Bs = (const uint4*)Bh;
        ra  = As[((m0 + lr)*K + lc) >> 3];
        rb0 = Bs[(lr*K + lc) >> 3];
        rb1 = Bs[((lr + 64)*K + lc) >> 3];
    }
    *(uint4*)&sm.m.A[0][lr*RS + lc]        = ra;
    *(uint4*)&sm.m.B[0][lr*RS + lc]        = rb0;
    *(uint4*)&sm.m.B[0][(lr + 64)*RS + lc] = rb1;
    __syncthreads();

    for (int c = 0; c < nch; c++) {
        bool more = (c + 1 < nch);
        if (more) {
            int cn = c + 1;
            int pass = cn / cpp;
            int kc = (cn - pass*cpp) * 32;
            const uint4* As = (const uint4*)(pass == 2 ? Al : Ah);
            const uint4* Bs = (const uint4*)(pass == 1 ? Bl : Bh);
            ra  = As[((m0 + lr)*K + kc + lc) >> 3];
            rb0 = Bs[(lr*K + kc + lc) >> 3];
            rb1 = Bs[((lr + 64)*K + kc + lc) >> 3];
        }
        uint32_t aBase = sAu0 + (c & 1)*bufA + (a_row*RS + a_col)*2;
        uint32_t bBase = sBu0 + (c & 1)*bufB + (b_row*RS + b_col)*2;
        #pragma unroll
        for (int h = 0; h < 2; h++) {
            uint32_t afr[2][4];
            ldmx4(afr[0], aBase + (h*16)*2);
            ldmx4(afr[1], aBase + (16*RS + h*16)*2);
            uint32_t bfr[2][4];
            ldmx4(bfr[0], bBase + (h*16)*2);
            ldmx4(bfr[1], bBase + (16*RS + h*16)*2);
            #pragma unroll
            for (int mi = 0; mi < 2; mi++)
                #pragma unroll
                for (int nj = 0; nj < 4; nj++)
                    mma16816(acc[mi][nj], afr[mi],
                             bfr[nj >> 1][(nj & 1)*2], bfr[nj >> 1][(nj & 1)*2 + 1]);
        }
        if (more) {
            int nb = (c + 1) & 1;
            *(uint4*)&sm.m.A[nb][lr*RS + lc]        = ra;
            *(uint4*)&sm.m.B[nb][lr*RS + lc]        = rb0;
            *(uint4*)&sm.m.B[nb][(lr + 64)*RS + lc] = rb1;
        }
        __syncthreads();
    }

    // epilogue: write C + per-thread column partials over this thread's 4 rows
    int g = lane >> 2, tig = lane & 3;
    float cs[4][2], cq[4][2];
    #pragma unroll
    for (int nj = 0; nj < 4; nj++)
        #pragma unroll
        for (int b = 0; b < 2; b++) { cs[nj][b] = 0.f; cq[nj][b] = 0.f; }
    #pragma unroll
    for (int mi = 0; mi < 2; mi++) {
        int r0 = m0 + wm*32 + mi*16 + g;
        #pragma unroll
        for (int nj = 0; nj < 4; nj++) {
            int col = wn*32 + nj*8 + tig*2;
            *(float2*)&C[r0*CO + col]       = make_float2(acc[mi][nj][0], acc[mi][nj][1]);
            *(float2*)&C[(r0 + 8)*CO + col] = make_float2(acc[mi][nj][2], acc[mi][nj][3]);
            #pragma unroll
            for (int b = 0; b < 2; b++) {
                float v0 = acc[mi][nj][b], v1 = acc[mi][nj][2 + b];
                cs[nj][b] += v0 + v1;
                cq[nj][b] += v0*v0 + v1*v1;
            }
        }
    }
    // deterministic block reduce (overlay union; mainloop smem no longer read)
    int r16 = wm*8 + g;
    #pragma unroll
    for (int nj = 0; nj < 4; nj++)
        #pragma unroll
        for (int b = 0; b < 2; b++) {
            int col = wn*32 + nj*8 + tig*2 + b;
            sm.r.sred[r16][col]  = cs[nj][b];
            sm.r.sqred[r16][col] = cq[nj][b];
        }
    __syncthreads();
    if (t < CO) {
        float ts = 0.f, tq = 0.f;
        #pragma unroll
        for (int r = 0; r < 16; r++) { ts += sm.r.sred[r][t]; tq += sm.r.sqred[r][t]; }
        g_psum[blockIdx.x*CO + t] = ts;
        g_psq [blockIdx.x*CO + t] = tq;
    }
}

// ---------------- 5) BN finalize ----------------
__global__ void k_bn_final(const float* __restrict__ gg, const float* __restrict__ bb, int stage) {
    __shared__ float ss[128], sq[128];
    int o = blockIdx.x;
    int t = threadIdx.x;           // 128
    float s = 0.f, q = 0.f;
    for (int i = t; i < NGB; i += 128) { s += g_psum[i*CO + o]; q += g_psq[i*CO + o]; }
    ss[t] = s; sq[t] = q;
    __syncthreads();
    for (int st = 64; st > 0; st >>= 1) {
        if (t < st) { ss[t] += ss[t+st]; sq[t] += sq[t+st]; }
        __syncthreads();
    }
    if (t == 0) {
        float inv = 1.0f / (float)HWX;
        float mu  = ss[0] * inv;
        float var = sq[0] * inv - mu*mu;
        float sc  = gg[o] * rsqrtf(var + 1e-5f);
        g_bn[stage*2*CO + o]      = sc;
        g_bn[stage*2*CO + CO + o] = bb[o] - mu*sc;
    }
}

// ---------------- 6) depthwise 3x3 on act(C) -> bf16 hi/lo ----------------
__global__ void k_dw(const float* __restrict__ Cin_, const float* __restrict__ dww,
                     __nv_bfloat16* __restrict__ Zh, __nv_bfloat16* __restrict__ Zl,
                     int stage) {
    __shared__ float dws[CO*9];
    int tid = threadIdx.x;          // 256
    int pg = tid >> 5;
    int cg = tid & 31;
    for (int i = tid; i < CO*9; i += 256) dws[i] = dww[i];
    __syncthreads();
    int p = blockIdx.x * 8 + pg;
    int h = p / WWD, w = p % WWD;
    int cb = cg * 4;
    float4 sc = *(const float4*)&g_bn[stage*2*CO + cb];
    float4 sh = *(const float4*)&g_bn[stage*2*CO + CO + cb];
    float4 acc = make_float4(0.f,0.f,0.f,0.f);
    #pragma unroll
    for (int t = 0; t < 9; t++) {
        int hh = h + t/3 - 1, ww = w + t%3 - 1;
        if (hh < 0 || hh >= HH || ww < 0 || ww >= WWD) continue;
        float4 v = *(const float4*)&Cin_[(hh*WWD + ww)*CO + cb];
        float ax = v.x*sc.x + sh.x; ax = (ax >= 0.f) ? ax : 0.01f*ax;
        float ay = v.y*sc.y + sh.y; ay = (ay >= 0.f) ? ay : 0.01f*ay;
        float az = v.z*sc.z + sh.z; az = (az >= 0.f) ? az : 0.01f*az;
        float aw = v.w*sc.w + sh.w; aw = (aw >= 0.f) ? aw : 0.01f*aw;
        acc.x += dws[(cb+0)*9+t] * ax;
        acc.y += dws[(cb+1)*9+t] * ay;
        acc.z += dws[(cb+2)*9+t] * az;
        acc.w += dws[(cb+3)*9+t] * aw;
    }
    union { __nv_bfloat162 b2[2]; uint2 u; } hv, lv;
    split_bf16(acc.x, hv.b2[0].x, lv.b2[0].x);
    split_bf16(acc.y, hv.b2[0].y, lv.b2[0].y);
    split_bf16(acc.z, hv.b2[1].x, lv.b2[1].x);
    split_bf16(acc.w, hv.b2[1].y, lv.b2[1].y);
    *(uint2*)&Zh[p*CO + cb] = hv.u;
    *(uint2*)&Zl[p*CO + cb] = lv.u;
}

// ---------------- 7) final act + transpose to NCHW ----------------
__global__ void k_final(float* __restrict__ out) {
    __shared__ float s[32][33];
    int ptile = blockIdx.x * 32;
    int ctile = blockIdx.y * 32;
    int tx = threadIdx.x, ty = threadIdx.y;  // 32 x 8
    #pragma unroll
    for (int i = 0; i < 32; i += 8) {
        int p = ptile + ty + i, c = ctile + tx;
        float v = g_C3[p*CO + c];
        float a = v*g_bn[2*2*CO + c] + g_bn[2*2*CO + CO + c];
        a = (a >= 0.f) ? a : 0.01f*a;
        s[ty+i][tx] = a;
    }
    __syncthreads();
    #pragma unroll
    for (int i = 0; i < 32; i += 8)
        out[(ctile + ty + i)*HWX + ptile + tx] = s[tx][ty+i];
}

// ---------------- launch ----------------
extern "C" void kernel_launch(void* const* d_in, const int* in_sizes, int n_in,
                              void* d_out, int out_size) {
    const float* x        = (const float*)d_in[0];
    const float* x_range  = (const float*)d_in[1];
    const float* range_o  = (const float*)d_in[2];
    const float* w_reduce = (const float*)d_in[3];
    const float* g_r      = (const float*)d_in[4];
    const float* b_r      = (const float*)d_in[5];
    const float* dw1      = (const float*)d_in[6];
    const float* pw1      = (const float*)d_in[7];
    const float* g1       = (const float*)d_in[8];
    const float* b1       = (const float*)d_in[9];
    const float* dw2      = (const float*)d_in[10];
    const float* pw2      = (const float*)d_in[11];
    const float* g2       = (const float*)d_in[12];
    const float* b2       = (const float*)d_in[13];
    float* out = (float*)d_out;

    float *C1, *C2, *C3;
    __nv_bfloat16 *y1, *y2, *w1h, *w1l, *w2h, *w2l, *w3h, *w3l, *z1h, *z1l, *z2h, *z2l;
    cudaGetSymbolAddress((void**)&C1, g_C1);
    cudaGetSymbolAddress((void**)&C2, g_C2);
    cudaGetSymbolAddress((void**)&C3, g_C3);
    cudaGetSymbolAddress((void**)&y1, g_y1);
    cudaGetSymbolAddress((void**)&y2, g_y2);
    cudaGetSymbolAddress((void**)&w1h, g_w1h);
    cudaGetSymbolAddress((void**)&w1l, g_w1l);
    cudaGetSymbolAddress((void**)&w2h, g_w2h);
    cudaGetSymbolAddress((void**)&w2l, g_w2l);
    cudaGetSymbolAddress((void**)&w3h, g_w3h);
    cudaGetSymbolAddress((void**)&w3l, g_w3l);
    cudaGetSymbolAddress((void**)&z1h, g_z1h);
    cudaGetSymbolAddress((void**)&z1l, g_z1l);
    cudaGetSymbolAddress((void**)&z2h, g_z2h);
    cudaGetSymbolAddress((void**)&z2l, g_z2l);

    k_prep<<<NB_PREP, 256>>>(x, x_range, w_reduce, pw1, pw2, range_o);
    k_gather<<<HWX/4, 256>>>();

    k_gemm_tc<<<NGB, 256>>>(y1, y2, w1h, w1l, C1, CIN);
    k_bn_final<<<CO, 128>>>(g_r, b_r, 0);
    k_dw<<<HWX/8, 256>>>(C1, dw1, z1h, z1l, 0);

    k_gemm_tc<<<NGB, 256>>>(z1h, z1l, w2h, w2l, C2, CO);
    k_bn_final<<<CO, 128>>>(g1, b1, 1);
    k_dw<<<HWX/8, 256>>>(C2, dw2, z2h, z2l, 1);

    k_gemm_tc<<<NGB, 256>>>(z2h, z2l, w3h, w3l, C3, CO);
    k_bn_final<<<CO, 128>>>(g2, b2, 2);

    k_final<<<dim3(HWX/32, CO/32), dim3(32,8)>>>(out);
}